// round 2
// baseline (speedup 1.0000x reference)
#include <cuda_runtime.h>

// Problem constants
#define Bb  2
#define Tt  2048
#define Ee  1024
#define Hh  8
#define Dd  512
#define HDc 4096          // H*D
#define Mc  4096          // B*T
#define Dh  256           // D/2

// Scratch (static device allocations — allowed; runtime alloc is not)
__device__ float g_q[(size_t)Mc * HDc];
__device__ float g_k[(size_t)Mc * HDc];
__device__ float g_v[(size_t)Mc * HDc];
__device__ float g_attn[(size_t)Mc * HDc];
__device__ float g_s[(size_t)Bb * Hh * Tt * Tt];   // 256 MiB scores/probs
__device__ float g_cos[Tt * Dh];
__device__ float g_sin[Tt * Dh];

// ---------------------------------------------------------------------------
// helpers
// ---------------------------------------------------------------------------
__device__ __forceinline__ unsigned f2tf(float x) {
    unsigned r;
    asm("cvt.rna.tf32.f32 %0, %1;" : "=r"(r) : "f"(x));
    return r;
}

__device__ __forceinline__ void mma8(float (&c)[4], const unsigned (&a)[4], const unsigned (&b)[2]) {
    asm volatile(
        "mma.sync.aligned.m16n8k8.row.col.f32.tf32.tf32.f32 "
        "{%0,%1,%2,%3}, {%4,%5,%6,%7}, {%8,%9}, {%0,%1,%2,%3};\n"
        : "+f"(c[0]), "+f"(c[1]), "+f"(c[2]), "+f"(c[3])
        : "r"(a[0]), "r"(a[1]), "r"(a[2]), "r"(a[3]), "r"(b[0]), "r"(b[1]));
}

// Fast-math-immune sincos via Cody-Waite reduction (valid for |a| < ~4000)
__device__ __forceinline__ void sincos_cw(float a, float* sp, float* cp) {
    float j = rintf(a * 0.63661977236758138f);   // 2/pi
    int   q = (int)j;
    float r = fmaf(j, -1.5707962512969971e+00f, a);
    r = fmaf(j, -7.5497894158615964e-08f, r);
    r = fmaf(j, -5.3903029534742385e-15f, r);
    float x2 = r * r;
    float s = r * (1.f + x2 * (-1.6666667e-1f + x2 * (8.3333333e-3f +
                    x2 * (-1.9841270e-4f + x2 * 2.7557319e-6f))));
    float c = 1.f + x2 * (-0.5f + x2 * (4.1666667e-2f +
                    x2 * (-1.3888889e-3f + x2 * 2.4801587e-5f)));
    switch (q & 3) {
        case 0: *sp =  s; *cp =  c; break;
        case 1: *sp =  c; *cp = -s; break;
        case 2: *sp = -s; *cp = -c; break;
        default:*sp = -c; *cp =  s; break;
    }
}

// ---------------------------------------------------------------------------
// Generic tf32 tensor-core GEMM.
//   BNN==0: C = alpha * A[M,K] * B[N,K]^T   (both K-major, "NT")
//   BNN==1: C = alpha * A[M,K] * B[K,N]     ("NN")
// CSKIP: skip output tiles strictly above the causal diagonal (scores GEMM)
// CK:    limit K loop to m0+128 (P@V GEMM, probs zero beyond row's block)
// Batched over blockIdx.z with offsets  off = (z>>3)*Outer + (z&7)*Inner.
// Tile: 128x128x32, 256 threads, 8 warps (2m x 4n), warp tile 64x32.
// ---------------------------------------------------------------------------
template <int BNN, bool CSKIP, bool CK>
__global__ __launch_bounds__(256, 1) void gemm_tf32(
    const float* __restrict__ Ag, const float* __restrict__ Bg, float* __restrict__ Cg,
    int Kdim, int lda, int ldb, int ldc,
    long long aO, long long aI, long long bO, long long bI, long long cO, long long cI,
    float alpha)
{
    const int m0 = blockIdx.y * 128;
    const int n0 = blockIdx.x * 128;
    if (CSKIP && n0 >= m0 + 128) return;

    const int z = blockIdx.z;
    const float* A = Ag + (long long)(z >> 3) * aO + (long long)(z & 7) * aI;
    const float* B = Bg + (long long)(z >> 3) * bO + (long long)(z & 7) * bI;
    float*       C = Cg + (long long)(z >> 3) * cO + (long long)(z & 7) * cI;

    int kLim = CK ? ((Kdim < m0 + 128) ? Kdim : (m0 + 128)) : Kdim;
    const int nk = kLim >> 5;

    __shared__ unsigned As[128 * 36];
    __shared__ unsigned Bs[(BNN ? 32 * 132 : 128 * 36)];

    const int tid  = threadIdx.x;
    const int lane = tid & 31, warp = tid >> 5;
    const int wm = warp & 1, wn = warp >> 1;
    const int gr = lane >> 2, tg = lane & 3;

    float4 ra[4], rb[4];

    auto loadA = [&](int kt) {
        const float* src = A + (size_t)m0 * lda + kt * 32;
#pragma unroll
        for (int p = 0; p < 4; p++) {
            int fid = tid + p * 256;
            int rr = fid >> 3, kc = (fid & 7) << 2;
            ra[p] = *(const float4*)(src + (size_t)rr * lda + kc);
        }
    };
    auto loadB = [&](int kt) {
        if (!BNN) {
            const float* src = B + (size_t)n0 * ldb + kt * 32;
#pragma unroll
            for (int p = 0; p < 4; p++) {
                int fid = tid + p * 256;
                int rr = fid >> 3, kc = (fid & 7) << 2;
                rb[p] = *(const float4*)(src + (size_t)rr * ldb + kc);
            }
        } else {
            const float* src = B + (size_t)(kt * 32) * ldb + n0;
#pragma unroll
            for (int p = 0; p < 4; p++) {
                int fid = tid + p * 256;
                int kr = fid >> 5, nc = (fid & 31) << 2;
                rb[p] = *(const float4*)(src + (size_t)kr * ldb + nc);
            }
        }
    };
    auto storeA = [&]() {
#pragma unroll
        for (int p = 0; p < 4; p++) {
            int fid = tid + p * 256;
            int rr = fid >> 3, kc = (fid & 7) << 2;
            uint4 u;
            u.x = f2tf(ra[p].x); u.y = f2tf(ra[p].y);
            u.z = f2tf(ra[p].z); u.w = f2tf(ra[p].w);
            *(uint4*)&As[rr * 36 + kc] = u;
        }
    };
    auto storeB = [&]() {
#pragma unroll
        for (int p = 0; p < 4; p++) {
            int fid = tid + p * 256;
            uint4 u;
            u.x = f2tf(rb[p].x); u.y = f2tf(rb[p].y);
            u.z = f2tf(rb[p].z); u.w = f2tf(rb[p].w);
            if (!BNN) {
                int rr = fid >> 3, kc = (fid & 7) << 2;
                *(uint4*)&Bs[rr * 36 + kc] = u;
            } else {
                int kr = fid >> 5, nc = (fid & 31) << 2;
                *(uint4*)&Bs[kr * 132 + nc] = u;
            }
        }
    };

    float acc[4][4][4] = {};

    auto compute = [&]() {
#pragma unroll
        for (int ks = 0; ks < 4; ks++) {
            const int k8 = ks * 8;
            unsigned a[4][4], b[4][2];
#pragma unroll
            for (int i = 0; i < 4; i++) {
                int r = wm * 64 + i * 16 + gr;
                a[i][0] = As[r * 36 + k8 + tg];
                a[i][1] = As[(r + 8) * 36 + k8 + tg];
                a[i][2] = As[r * 36 + k8 + tg + 4];
                a[i][3] = As[(r + 8) * 36 + k8 + tg + 4];
            }
#pragma unroll
            for (int j = 0; j < 4; j++) {
                int cN = wn * 32 + j * 8 + gr;
                if (!BNN) {
                    b[j][0] = Bs[cN * 36 + k8 + tg];
                    b[j][1] = Bs[cN * 36 + k8 + tg + 4];
                } else {
                    b[j][0] = Bs[(k8 + tg) * 132 + cN];
                    b[j][1] = Bs[(k8 + tg + 4) * 132 + cN];
                }
            }
#pragma unroll
            for (int i = 0; i < 4; i++)
#pragma unroll
                for (int j = 0; j < 4; j++) mma8(acc[i][j], a[i], b[j]);
        }
    };

    loadA(0); loadB(0);
    storeA(); storeB();
    __syncthreads();
    for (int kt = 0; kt < nk; kt++) {
        bool more = (kt + 1 < nk);
        if (more) { loadA(kt + 1); loadB(kt + 1); }
        compute();
        __syncthreads();
        if (more) { storeA(); storeB(); __syncthreads(); }
    }

#pragma unroll
    for (int i = 0; i < 4; i++) {
        int r0 = m0 + wm * 64 + i * 16 + gr;
#pragma unroll
        for (int j = 0; j < 4; j++) {
            int c0 = n0 + wn * 32 + j * 8 + tg * 2;
            float2 v01 = make_float2(acc[i][j][0] * alpha, acc[i][j][1] * alpha);
            float2 v23 = make_float2(acc[i][j][2] * alpha, acc[i][j][3] * alpha);
            *(float2*)(C + (size_t)r0 * ldc + c0) = v01;
            *(float2*)(C + (size_t)(r0 + 8) * ldc + c0) = v23;
        }
    }
}

// ---------------------------------------------------------------------------
// RoPE cos/sin table: one entry per (t, freq). Accurate exp2 + Cody-Waite
// sincos so results are stable regardless of --use_fast_math.
// ---------------------------------------------------------------------------
__global__ void rope_table() {
    int idx = blockIdx.x * 256 + threadIdx.x;   // Tt*Dh entries
    int d = idx & 255, t = idx >> 8;
    float e = (float)d * (1.0f / 256.0f);
    // p = -e * log2(10000), split-constant for accuracy
    const float LH = 13.287712097167969f;
    const float LL = 2.8238148e-7f;
    float p = -fmaf(e, LH, e * LL);
    // accurate 2^p for p in [-13.3, 0]
    float nf = floorf(p);
    float f  = p - nf;
    float y  = f * 0.69314718055994531f;
    float er = 1.f + y * (1.f + y * (0.5f + y * (0.16666667f + y * (0.041666667f +
               y * (0.0083333333f + y * (0.0013888889f + y * (1.9841270e-4f +
               y * (2.4801587e-5f + y * 2.7557319e-6f))))))));
    float invf = er * __int_as_float(((int)nf + 127) << 23);
    float ang = (float)t * invf;
    float s, c;
    sincos_cw(ang, &s, &c);
    g_cos[idx] = c;
    g_sin[idx] = s;
}

// In-place RoPE on q and k (flat [b*T+t, h*D+d] layout), half-split pairs.
__global__ void rope_apply() {
    int idx = blockIdx.x * 256 + threadIdx.x;   // B*T*H*Dh = 8388608
    int d = idx & 255;
    int h = (idx >> 8) & 7;
    int t = (idx >> 11) & 2047;
    int b = idx >> 22;
    float cc = g_cos[t * 256 + d], ss = g_sin[t * 256 + d];
    size_t base = ((size_t)(b * Tt + t)) * HDc + h * Dd + d;
    float x1 = g_q[base], x2 = g_q[base + 256];
    g_q[base]       = x1 * cc - x2 * ss;
    g_q[base + 256] = x1 * ss + x2 * cc;
    x1 = g_k[base]; x2 = g_k[base + 256];
    g_k[base]       = x1 * cc - x2 * ss;
    g_k[base + 256] = x1 * ss + x2 * cc;
}

// ---------------------------------------------------------------------------
// Causal softmax: one block per row. Zeroes probs only up to the next 128
// boundary (all the P@V GEMM will ever read for this row).
// ---------------------------------------------------------------------------
__global__ void softmax_causal(float* __restrict__ S) {
    long long r = blockIdx.x;
    long long z = r >> 11;
    int i = (int)(r & 2047);
    float* row = S + (size_t)z * Tt * Tt + (size_t)i * Tt;
    const int L = i + 1;
    const int tid = threadIdx.x;
    __shared__ float red[256];

    float v[8];
    float mx = -3.4e38f;
#pragma unroll
    for (int p = 0; p < 8; p++) {
        int j = tid + p * 256;
        v[p] = (j < L) ? row[j] : -3.4e38f;
        mx = fmaxf(mx, v[p]);
    }
    red[tid] = mx; __syncthreads();
    for (int s = 128; s > 0; s >>= 1) {
        if (tid < s) red[tid] = fmaxf(red[tid], red[tid + s]);
        __syncthreads();
    }
    mx = red[0]; __syncthreads();

    float sum = 0.f;
#pragma unroll
    for (int p = 0; p < 8; p++) {
        int j = tid + p * 256;
        float e = (j < L) ? expf(v[p] - mx) : 0.f;
        v[p] = e;
        sum += e;
    }
    red[tid] = sum; __syncthreads();
    for (int s = 128; s > 0; s >>= 1) {
        if (tid < s) red[tid] += red[tid + s];
        __syncthreads();
    }
    float inv = 1.0f / red[0];

    int Lpad = (L + 127) & ~127;
#pragma unroll
    for (int p = 0; p < 8; p++) {
        int j = tid + p * 256;
        if (j < Lpad) row[j] = v[p] * inv;
    }
}

// ---------------------------------------------------------------------------
extern "C" void kernel_launch(void* const* d_in, const int* in_sizes, int n_in,
                              void* d_out, int out_size) {
    const float* x  = (const float*)d_in[0];
    const float* Wq = (const float*)d_in[1];
    const float* Wk = (const float*)d_in[2];
    const float* Wv = (const float*)d_in[3];
    const float* Wo = (const float*)d_in[4];
    float* out = (float*)d_out;

    float *q, *k, *v, *attn, *s;
    cudaGetSymbolAddress((void**)&q, g_q);
    cudaGetSymbolAddress((void**)&k, g_k);
    cudaGetSymbolAddress((void**)&v, g_v);
    cudaGetSymbolAddress((void**)&attn, g_attn);
    cudaGetSymbolAddress((void**)&s, g_s);

    dim3 blk(256);
    const long long TT = (long long)Tt * Tt;
    const long long THD = (long long)Tt * HDc;

    // 1) QKV projections: [4096,4096] = x[4096,1024] @ W^T
    gemm_tf32<0, false, false><<<dim3(HDc / 128, Mc / 128, 1), blk>>>(
        x, Wq, q, Ee, Ee, Ee, HDc, 0, 0, 0, 0, 0, 0, 1.f);
    gemm_tf32<0, false, false><<<dim3(HDc / 128, Mc / 128, 1), blk>>>(
        x, Wk, k, Ee, Ee, Ee, HDc, 0, 0, 0, 0, 0, 0, 1.f);
    gemm_tf32<0, false, false><<<dim3(HDc / 128, Mc / 128, 1), blk>>>(
        x, Wv, v, Ee, Ee, Ee, HDc, 0, 0, 0, 0, 0, 0, 1.f);

    // 2) RoPE
    rope_table<<<(Tt * Dh) / 256, 256>>>();
    rope_apply<<<(Bb * Tt * Hh * Dh) / 256, 256>>>();

    // 3) scores[b,h] = scale * q[b,h] @ k[b,h]^T  (causal tile skip)
    gemm_tf32<0, true, false><<<dim3(Tt / 128, Tt / 128, Bb * Hh), blk>>>(
        q, k, s, Dd, HDc, HDc, Tt,
        THD, (long long)Dd, THD, (long long)Dd,
        (long long)Hh * TT, TT, 0.04419417382415922f);

    // 4) causal softmax
    softmax_causal<<<Bb * Hh * Tt, 256>>>(s);

    // 5) attn[b,h] = P[b,h] @ v[b,h]  (causal k limit)
    gemm_tf32<1, false, true><<<dim3(Dd / 128, Tt / 128, Bb * Hh), blk>>>(
        s, v, attn, Tt, Tt, HDc, HDc,
        (long long)Hh * TT, TT, THD, (long long)Dd, THD, (long long)Dd, 1.f);

    // 6) out = attn_flat @ Wo^T
    gemm_tf32<0, false, false><<<dim3(Ee / 128, Mc / 128, 1), blk>>>(
        attn, Wo, out, HDc, HDc, HDc, Ee, 0, 0, 0, 0, 0, 0, 1.f);
}

// round 4
// speedup vs baseline: 1.8764x; 1.8764x over previous
#include <cuda_runtime.h>
#include <cuda_fp16.h>
#include <cstdint>

// Problem constants
#define Bb  2
#define Tt  2048
#define Ee  1024
#define Hh  8
#define Dd  512
#define HDc 4096          // H*D
#define Mc  4096          // B*T
#define Dh  256           // D/2

// fp16 scratch (static device allocations)
__device__ __align__(1024) __half g_xh[(size_t)Mc * Ee];
__device__ __align__(1024) __half g_wqh[(size_t)HDc * Ee];
__device__ __align__(1024) __half g_wkh[(size_t)HDc * Ee];
__device__ __align__(1024) __half g_wvh[(size_t)HDc * Ee];
__device__ __align__(1024) __half g_woh[(size_t)Ee * HDc];
__device__ __align__(1024) __half g_qh[(size_t)Mc * HDc];
__device__ __align__(1024) __half g_kh[(size_t)Mc * HDc];
__device__ __align__(1024) __half g_vTh[(size_t)HDc * Mc];     // [h*D, b*T]
__device__ __align__(1024) __half g_attnh[(size_t)Mc * HDc];
__device__ __align__(1024) __half g_sh[(size_t)Bb * Hh * Tt * Tt];   // 128 MiB
__device__ float g_cos[Tt * Dh];
__device__ float g_sin[Tt * Dh];

// ---------------------------------------------------------------------------
// PTX helpers (base ISA only: cp.async, ldmatrix, mma.sync — all sm_80+)
// ---------------------------------------------------------------------------
__device__ __forceinline__ uint32_t smem_u32(const void* p) {
    uint32_t a;
    asm("{ .reg .u64 t; cvta.to.shared.u64 t, %1; cvt.u32.u64 %0, t; }" : "=r"(a) : "l"(p));
    return a;
}
__device__ __forceinline__ void cpasync16(uint32_t dst, const void* src) {
    asm volatile("cp.async.cg.shared.global [%0], [%1], 16;" :: "r"(dst), "l"(src));
}
#define CP_COMMIT() asm volatile("cp.async.commit_group;" ::: "memory")
#define CP_WAIT2()  asm volatile("cp.async.wait_group 2;" ::: "memory")

__device__ __forceinline__ void ldsm4(uint32_t& r0, uint32_t& r1, uint32_t& r2, uint32_t& r3,
                                      uint32_t addr) {
    asm volatile("ldmatrix.sync.aligned.m8n8.x4.shared.b16 {%0,%1,%2,%3}, [%4];"
                 : "=r"(r0), "=r"(r1), "=r"(r2), "=r"(r3) : "r"(addr));
}
__device__ __forceinline__ void mma168(float (&c)[4], const uint32_t (&a)[4], const uint32_t (&b)[2]) {
    asm volatile(
        "mma.sync.aligned.m16n8k16.row.col.f32.f16.f16.f32 "
        "{%0,%1,%2,%3}, {%4,%5,%6,%7}, {%8,%9}, {%0,%1,%2,%3};\n"
        : "+f"(c[0]), "+f"(c[1]), "+f"(c[2]), "+f"(c[3])
        : "r"(a[0]), "r"(a[1]), "r"(a[2]), "r"(a[3]), "r"(b[0]), "r"(b[1]));
}

// ---------------------------------------------------------------------------
// fp16 tensor-core GEMM:  C = alpha * A[M,K] * B[N,K]^T   (both K-major, NT)
// CSKIP: skip tiles strictly above causal diagonal.  CK: limit K to m0+128.
// OUT16: store C as fp16 (else fp32).
// Tile 128x128x32, 256 threads, 8 warps (2m x 4n), warp tile 64x32,
// 4-stage cp.async pipeline, ldmatrix.x4, padded smem rows (80B stride).
// Batch over blockIdx.z: off = (z>>3)*Outer + (z&7)*Inner.
// ---------------------------------------------------------------------------
#define STG_B   20480                       // (A 128*80) + (B 128*80)
#define GEMM_SMEM (4 * STG_B)               // 81920

template <bool CSKIP, bool CK, bool OUT16>
__global__ __launch_bounds__(256, 1) void gemm_fp16(
    const __half* __restrict__ Ag, const __half* __restrict__ Bg, void* __restrict__ Cg,
    int Kdim, int lda, int ldb, int ldc,
    long long aO, long long aI, long long bO, long long bI, long long cO, long long cI,
    float alpha)
{
    const int m0 = blockIdx.y * 128;
    const int n0 = blockIdx.x * 128;
    if (CSKIP && n0 >= m0 + 128) return;

    const int z = blockIdx.z;
    const __half* A = Ag + (long long)(z >> 3) * aO + (long long)(z & 7) * aI;
    const __half* B = Bg + (long long)(z >> 3) * bO + (long long)(z & 7) * bI;

    const int kLim = CK ? ((Kdim < m0 + 128) ? Kdim : (m0 + 128)) : Kdim;
    const int nk = kLim >> 5;

    extern __shared__ char smem[];
    const uint32_t sb = smem_u32(smem);
    const int tid = threadIdx.x, wid = tid >> 5, lane = tid & 31;
    const int wm = wid & 1, wn = wid >> 1;

    auto load_stage = [&](int kt) {
        uint32_t stA = sb + (kt & 3) * STG_B;
        uint32_t stB = stA + 10240;
        const __half* Asrc = A + (size_t)m0 * lda + kt * 32;
        const __half* Bsrc = B + (size_t)n0 * ldb + kt * 32;
#pragma unroll
        for (int p = 0; p < 2; p++) {
            int id = tid + p * 256;          // 512 chunks of 16B
            int r = id >> 2, c = (id & 3) * 8;
            cpasync16(stA + r * 80 + c * 2, Asrc + (size_t)r * lda + c);
        }
#pragma unroll
        for (int p = 0; p < 2; p++) {
            int id = tid + p * 256;
            int r = id >> 2, c = (id & 3) * 8;
            cpasync16(stB + r * 80 + c * 2, Bsrc + (size_t)r * ldb + c);
        }
    };

#pragma unroll
    for (int s = 0; s < 3; s++) { if (s < nk) load_stage(s); CP_COMMIT(); }

    float acc[4][4][4] = {};

    // per-lane ldmatrix address components
    const int lrow = lane & 15;              // row within 16-row group
    const int lcol = (lane >> 4) * 8;        // 8-half column offset (k dim)

    for (int kt = 0; kt < nk; kt++) {
        CP_WAIT2();
        __syncthreads();
        uint32_t stA = sb + (kt & 3) * STG_B;
        uint32_t stB = stA + 10240;
        const uint32_t aBase = stA + (wm * 64 + lrow) * 80;
        const uint32_t bBase = stB + (wn * 32 + lrow) * 80;
#pragma unroll
        for (int kk = 0; kk < 2; kk++) {
            const int kOff = (kk * 16 + lcol) * 2;
            uint32_t a[4][4], b[4][2];
#pragma unroll
            for (int i = 0; i < 4; i++)
                ldsm4(a[i][0], a[i][1], a[i][2], a[i][3], aBase + i * 16 * 80 + kOff);
#pragma unroll
            for (int jp = 0; jp < 2; jp++) {
                uint32_t t0, t1, t2, t3;
                ldsm4(t0, t1, t2, t3, bBase + jp * 16 * 80 + kOff);
                b[jp * 2][0] = t0; b[jp * 2 + 1][0] = t1;
                b[jp * 2][1] = t2; b[jp * 2 + 1][1] = t3;
            }
#pragma unroll
            for (int i = 0; i < 4; i++)
#pragma unroll
                for (int j = 0; j < 4; j++) mma168(acc[i][j], a[i], b[j]);
        }
        __syncthreads();
        if (kt + 3 < nk) load_stage(kt + 3);
        CP_COMMIT();
    }

    // epilogue: direct global stores from accumulators
    const int er = lane >> 2, ec = (lane & 3) * 2;
    if (OUT16) {
        __half* C = (__half*)Cg + (long long)(z >> 3) * cO + (long long)(z & 7) * cI;
#pragma unroll
        for (int i = 0; i < 4; i++) {
            int r0 = m0 + wm * 64 + i * 16 + er;
#pragma unroll
            for (int j = 0; j < 4; j++) {
                int c0 = n0 + wn * 32 + j * 8 + ec;
                __half2 h01 = __floats2half2_rn(acc[i][j][0] * alpha, acc[i][j][1] * alpha);
                __half2 h23 = __floats2half2_rn(acc[i][j][2] * alpha, acc[i][j][3] * alpha);
                *(__half2*)(C + (size_t)r0 * ldc + c0) = h01;
                *(__half2*)(C + (size_t)(r0 + 8) * ldc + c0) = h23;
            }
        }
    } else {
        float* C = (float*)Cg + (long long)(z >> 3) * cO + (long long)(z & 7) * cI;
#pragma unroll
        for (int i = 0; i < 4; i++) {
            int r0 = m0 + wm * 64 + i * 16 + er;
#pragma unroll
            for (int j = 0; j < 4; j++) {
                int c0 = n0 + wn * 32 + j * 8 + ec;
                *(float2*)(C + (size_t)r0 * ldc + c0) =
                    make_float2(acc[i][j][0] * alpha, acc[i][j][1] * alpha);
                *(float2*)(C + (size_t)(r0 + 8) * ldc + c0) =
                    make_float2(acc[i][j][2] * alpha, acc[i][j][3] * alpha);
            }
        }
    }
}

// ---------------------------------------------------------------------------
// fp32 -> fp16 conversion
// ---------------------------------------------------------------------------
__global__ void f2h(const float4* __restrict__ in, uint2* __restrict__ outp, int n4) {
    int i = blockIdx.x * 256 + threadIdx.x;
    if (i < n4) {
        float4 v = in[i];
        __half2 a = __floats2half2_rn(v.x, v.y);
        __half2 b = __floats2half2_rn(v.z, v.w);
        outp[i] = make_uint2(*(uint32_t*)&a, *(uint32_t*)&b);
    }
}

// ---------------------------------------------------------------------------
// RoPE (fast-math-immune)
// ---------------------------------------------------------------------------
__device__ __forceinline__ void sincos_cw(float a, float* sp, float* cp) {
    float j = rintf(a * 0.63661977236758138f);
    int   q = (int)j;
    float r = fmaf(j, -1.5707962512969971e+00f, a);
    r = fmaf(j, -7.5497894158615964e-08f, r);
    r = fmaf(j, -5.3903029534742385e-15f, r);
    float x2 = r * r;
    float s = r * (1.f + x2 * (-1.6666667e-1f + x2 * (8.3333333e-3f +
                    x2 * (-1.9841270e-4f + x2 * 2.7557319e-6f))));
    float c = 1.f + x2 * (-0.5f + x2 * (4.1666667e-2f +
                    x2 * (-1.3888889e-3f + x2 * 2.4801587e-5f)));
    switch (q & 3) {
        case 0: *sp =  s; *cp =  c; break;
        case 1: *sp =  c; *cp = -s; break;
        case 2: *sp = -s; *cp = -c; break;
        default:*sp = -c; *cp =  s; break;
    }
}

__global__ void rope_table() {
    int idx = blockIdx.x * 256 + threadIdx.x;
    int d = idx & 255, t = idx >> 8;
    float e = (float)d * (1.0f / 256.0f);
    const float LH = 13.287712097167969f;
    const float LL = 2.8238148e-7f;
    float p = -fmaf(e, LH, e * LL);
    float nf = floorf(p);
    float f  = p - nf;
    float y  = f * 0.69314718055994531f;
    float er = 1.f + y * (1.f + y * (0.5f + y * (0.16666667f + y * (0.041666667f +
               y * (0.0083333333f + y * (0.0013888889f + y * (1.9841270e-4f +
               y * (2.4801587e-5f + y * 2.7557319e-6f))))))));
    float invf = er * __int_as_float(((int)nf + 127) << 23);
    float ang = (float)t * invf;
    float s, c;
    sincos_cw(ang, &s, &c);
    g_cos[idx] = c;
    g_sin[idx] = s;
}

// In-place RoPE on fp16 q and k (flat [b*T+t, h*D+d]), half-split pairs.
__global__ void rope_apply() {
    int idx = blockIdx.x * 256 + threadIdx.x;   // B*T*H*Dh
    int d = idx & 255;
    int h = (idx >> 8) & 7;
    int t = (idx >> 11) & 2047;
    int b = idx >> 22;
    float cc = g_cos[t * 256 + d], ss = g_sin[t * 256 + d];
    size_t base = ((size_t)(b * Tt + t)) * HDc + h * Dd + d;
    float x1 = __half2float(g_qh[base]), x2 = __half2float(g_qh[base + 256]);
    g_qh[base]       = __float2half_rn(x1 * cc - x2 * ss);
    g_qh[base + 256] = __float2half_rn(x1 * ss + x2 * cc);
    x1 = __half2float(g_kh[base]); x2 = __half2float(g_kh[base + 256]);
    g_kh[base]       = __float2half_rn(x1 * cc - x2 * ss);
    g_kh[base + 256] = __float2half_rn(x1 * ss + x2 * cc);
}

// ---------------------------------------------------------------------------
// Causal softmax on fp16 S; zero-pads probs to this row's 128 boundary.
// One block (256 thr) per row of 2048.
// ---------------------------------------------------------------------------
__global__ void softmax_causal(__half2* __restrict__ S) {
    long long rr = blockIdx.x;
    long long zz = rr >> 11;
    int i = (int)(rr & 2047);
    __half2* row = S + zz * (Tt * Tt / 2) + (size_t)i * (Tt / 2);
    const int L = i + 1;
    const int tid = threadIdx.x;
    __shared__ float red[256];

    float v[8];
    float mx = -3.4e38f;
#pragma unroll
    for (int p = 0; p < 4; p++) {
        int j2 = tid + p * 256;                  // half2 index; elems 2j2, 2j2+1
        float2 f = __half22float2(row[j2]);
        v[p * 2]     = (2 * j2     < L) ? f.x : -3.4e38f;
        v[p * 2 + 1] = (2 * j2 + 1 < L) ? f.y : -3.4e38f;
        mx = fmaxf(mx, fmaxf(v[p * 2], v[p * 2 + 1]));
    }
    red[tid] = mx; __syncthreads();
    for (int s = 128; s > 0; s >>= 1) {
        if (tid < s) red[tid] = fmaxf(red[tid], red[tid + s]);
        __syncthreads();
    }
    mx = red[0]; __syncthreads();

    float sum = 0.f;
#pragma unroll
    for (int p = 0; p < 8; p++) {
        float e = (v[p] > -1e38f) ? expf(v[p] - mx) : 0.f;
        v[p] = e;
        sum += e;
    }
    red[tid] = sum; __syncthreads();
    for (int s = 128; s > 0; s >>= 1) {
        if (tid < s) red[tid] += red[tid + s];
        __syncthreads();
    }
    float inv = 1.0f / red[0];

    const int Lpad = (L + 127) & ~127;           // always the row-tile end
#pragma unroll
    for (int p = 0; p < 4; p++) {
        int j2 = tid + p * 256;
        if (2 * j2 < Lpad)
            row[j2] = __floats2half2_rn(v[p * 2] * inv, v[p * 2 + 1] * inv);
    }
}

// ---------------------------------------------------------------------------
extern "C" void kernel_launch(void* const* d_in, const int* in_sizes, int n_in,
                              void* d_out, int out_size) {
    const float* x  = (const float*)d_in[0];
    const float* Wq = (const float*)d_in[1];
    const float* Wk = (const float*)d_in[2];
    const float* Wv = (const float*)d_in[3];
    const float* Wo = (const float*)d_in[4];
    float* out = (float*)d_out;

    __half *xh, *wqh, *wkh, *wvh, *woh, *qh, *kh, *vTh, *attnh, *sh;
    cudaGetSymbolAddress((void**)&xh, g_xh);
    cudaGetSymbolAddress((void**)&wqh, g_wqh);
    cudaGetSymbolAddress((void**)&wkh, g_wkh);
    cudaGetSymbolAddress((void**)&wvh, g_wvh);
    cudaGetSymbolAddress((void**)&woh, g_woh);
    cudaGetSymbolAddress((void**)&qh, g_qh);
    cudaGetSymbolAddress((void**)&kh, g_kh);
    cudaGetSymbolAddress((void**)&vTh, g_vTh);
    cudaGetSymbolAddress((void**)&attnh, g_attnh);
    cudaGetSymbolAddress((void**)&sh, g_sh);

    cudaFuncSetAttribute(gemm_fp16<false, false, true>,
                         cudaFuncAttributeMaxDynamicSharedMemorySize, GEMM_SMEM);
    cudaFuncSetAttribute(gemm_fp16<true, false, true>,
                         cudaFuncAttributeMaxDynamicSharedMemorySize, GEMM_SMEM);
    cudaFuncSetAttribute(gemm_fp16<false, true, true>,
                         cudaFuncAttributeMaxDynamicSharedMemorySize, GEMM_SMEM);
    cudaFuncSetAttribute(gemm_fp16<false, false, false>,
                         cudaFuncAttributeMaxDynamicSharedMemorySize, GEMM_SMEM);

    dim3 blk(256);
    const long long TT  = (long long)Tt * Tt;
    const long long THD = (long long)Tt * HDc;

    // 0) convert raw fp32 inputs to fp16 scratch (x rounding == operand rounding)
    const int n4 = HDc * Ee / 4;     // 1M float4 per 16MB tensor
    f2h<<<n4 / 256, 256>>>((const float4*)x,  (uint2*)xh,  n4);
    f2h<<<n4 / 256, 256>>>((const float4*)Wq, (uint2*)wqh, n4);
    f2h<<<n4 / 256, 256>>>((const float4*)Wk, (uint2*)wkh, n4);
    f2h<<<n4 / 256, 256>>>((const float4*)Wv, (uint2*)wvh, n4);
    f2h<<<n4 / 256, 256>>>((const float4*)Wo, (uint2*)woh, n4);

    // 1) QKV projections (NT)
    gemm_fp16<false, false, true><<<dim3(32, 32, 1), blk, GEMM_SMEM>>>(
        xh, wqh, qh, Ee, Ee, Ee, HDc, 0, 0, 0, 0, 0, 0, 1.f);
    gemm_fp16<false, false, true><<<dim3(32, 32, 1), blk, GEMM_SMEM>>>(
        xh, wkh, kh, Ee, Ee, Ee, HDc, 0, 0, 0, 0, 0, 0, 1.f);
    // vT[hd, m] = Wv[hd,:] . x[m,:]
    gemm_fp16<false, false, true><<<dim3(32, 32, 1), blk, GEMM_SMEM>>>(
        wvh, xh, vTh, Ee, Ee, Ee, Mc, 0, 0, 0, 0, 0, 0, 1.f);

    // 2) RoPE on q, k
    rope_table<<<(Tt * Dh) / 256, 256>>>();
    rope_apply<<<(Bb * Tt * Hh * Dh) / 256, 256>>>();

    // 3) scores[b,h] = scale * q[b,h] @ k[b,h]^T   (causal tile skip)
    gemm_fp16<true, false, true><<<dim3(16, 16, Bb * Hh), blk, GEMM_SMEM>>>(
        qh, kh, sh, Dd, HDc, HDc, Tt,
        THD, (long long)Dd, THD, (long long)Dd,
        (long long)Hh * TT, TT, 0.044194173824159216f);

    // 4) causal softmax (fp16 in/out)
    softmax_causal<<<Bb * Hh * Tt, 256>>>((__half2*)sh);

    // 5) attn[b,h] = P[b,h] @ vT[b,h]^T   (NT, causal K limit)
    gemm_fp16<false, true, true><<<dim3(4, 16, Bb * Hh), blk, GEMM_SMEM>>>(
        sh, vTh, attnh, Tt, Tt, Mc, HDc,
        (long long)Hh * TT, TT,
        (long long)Tt, (long long)Dd * Mc,
        (long long)Tt * HDc, (long long)Dd, 1.f);

    // 6) out = attn_flat @ Wo^T  (fp32 output)
    gemm_fp16<false, false, false><<<dim3(8, 32, 1), blk, GEMM_SMEM>>>(
        attnh, woh, out, HDc, HDc, HDc, Ee, 0, 0, 0, 0, 0, 0, 1.f);
}

// round 5
// speedup vs baseline: 3.3268x; 1.7730x over previous
#include <cuda_runtime.h>
#include <cuda_fp16.h>
#include <cstdint>

// Problem constants
#define Bb  2
#define Tt  2048
#define Ee  1024
#define Hh  8
#define Dd  512
#define HDc 4096          // H*D
#define Mc  4096          // B*T
#define Dh  256           // D/2

// fp16 scratch (static device allocations)
__device__ __align__(1024) __half g_xh[(size_t)Mc * Ee];
__device__ __align__(1024) __half g_wqh[(size_t)HDc * Ee];
__device__ __align__(1024) __half g_wkh[(size_t)HDc * Ee];
__device__ __align__(1024) __half g_wvh[(size_t)HDc * Ee];
__device__ __align__(1024) __half g_woh[(size_t)Ee * HDc];
__device__ __align__(1024) __half g_qh[(size_t)Mc * HDc];
__device__ __align__(1024) __half g_kh[(size_t)Mc * HDc];
__device__ __align__(1024) __half g_vTh[(size_t)HDc * Mc];     // [h*D, b*T]
__device__ __align__(1024) __half g_attnh[(size_t)Mc * HDc];
__device__ __align__(1024) __half g_sh[(size_t)Bb * Hh * Tt * Tt];   // 128 MiB
__device__ float g_cos[Tt * Dh];
__device__ float g_sin[Tt * Dh];

// ---------------------------------------------------------------------------
// PTX helpers
// ---------------------------------------------------------------------------
__device__ __forceinline__ uint32_t smem_u32(const void* p) {
    uint32_t a;
    asm("{ .reg .u64 t; cvta.to.shared.u64 t, %1; cvt.u32.u64 %0, t; }" : "=r"(a) : "l"(p));
    return a;
}
__device__ __forceinline__ void cpasync16(uint32_t dst, const void* src) {
    asm volatile("cp.async.cg.shared.global [%0], [%1], 16;" :: "r"(dst), "l"(src));
}
#define CP_COMMIT() asm volatile("cp.async.commit_group;" ::: "memory")
#define CP_WAIT3()  asm volatile("cp.async.wait_group 3;" ::: "memory")

__device__ __forceinline__ void ldsm4(uint32_t& r0, uint32_t& r1, uint32_t& r2, uint32_t& r3,
                                      uint32_t addr) {
    asm volatile("ldmatrix.sync.aligned.m8n8.x4.shared.b16 {%0,%1,%2,%3}, [%4];"
                 : "=r"(r0), "=r"(r1), "=r"(r2), "=r"(r3) : "r"(addr));
}
__device__ __forceinline__ void mma168(float (&c)[4], const uint32_t (&a)[4], const uint32_t (&b)[2]) {
    asm volatile(
        "mma.sync.aligned.m16n8k16.row.col.f32.f16.f16.f32 "
        "{%0,%1,%2,%3}, {%4,%5,%6,%7}, {%8,%9}, {%0,%1,%2,%3};\n"
        : "+f"(c[0]), "+f"(c[1]), "+f"(c[2]), "+f"(c[3])
        : "r"(a[0]), "r"(a[1]), "r"(a[2]), "r"(a[3]), "r"(b[0]), "r"(b[1]));
}

// Swizzled smem offset for a (row, 16B-chunk) pair: 64B rows, chunk XOR (r>>1)&3.
// Makes the 8 rows of each ldmatrix phase hit 8 distinct (parity, chunk) bank
// groups -> conflict-free LDSM and STS.
__device__ __forceinline__ uint32_t swz(int r, int c) {
    return (uint32_t)(r * 64 + ((c ^ ((r >> 1) & 3)) << 4));
}

// ---------------------------------------------------------------------------
// fp16 tensor-core GEMM:  C = alpha * A[M,K] * B[N,K]^T   (both K-major, NT)
// CSKIP: skip tiles strictly above causal diagonal.  CK: limit K to m0+128.
// OUT16: store C as fp16 (else fp32).
// Tile 128x128x32, 256 threads, 8 warps (2m x 4n), warp tile 64x32,
// 5-stage cp.async pipeline, swizzled 64B smem rows, ONE sync per k-chunk,
// 2 CTAs/SM. Batch over blockIdx.z: off = (z>>3)*Outer + (z&7)*Inner.
// ---------------------------------------------------------------------------
#define NSTG   5
#define STG_B  16384                        // A 128*64 + B 128*64
#define GEMM_SMEM (NSTG * STG_B)            // 81920 -> 2 CTAs/SM (160KB)

template <bool CSKIP, bool CK, bool OUT16>
__global__ __launch_bounds__(256, 2) void gemm_fp16(
    const __half* __restrict__ Ag, const __half* __restrict__ Bg, void* __restrict__ Cg,
    int Kdim, int lda, int ldb, int ldc,
    long long aO, long long aI, long long bO, long long bI, long long cO, long long cI,
    float alpha)
{
    const int m0 = blockIdx.y * 128;
    const int n0 = blockIdx.x * 128;
    if (CSKIP && n0 >= m0 + 128) return;

    const int z = blockIdx.z;
    const __half* A = Ag + (long long)(z >> 3) * aO + (long long)(z & 7) * aI;
    const __half* B = Bg + (long long)(z >> 3) * bO + (long long)(z & 7) * bI;

    const int kLim = CK ? ((Kdim < m0 + 128) ? Kdim : (m0 + 128)) : Kdim;
    const int nk = kLim >> 5;

    extern __shared__ char smem[];
    const uint32_t sb = smem_u32(smem);
    const int tid = threadIdx.x, wid = tid >> 5, lane = tid & 31;
    const int wm = wid & 1, wn = wid >> 1;

    // cp.async: 512 16B chunks per tile half; 256 threads x 2
    const int ldr = tid >> 2;                // row 0..63 (+64 for p=1)
    const int ldc4 = tid & 3;                // chunk 0..3
    auto load_stage = [&](int kt) {
        uint32_t stA = sb + (kt % NSTG) * STG_B;
        uint32_t stB = stA + 8192;
        const __half* Asrc = A + (size_t)m0 * lda + kt * 32;
        const __half* Bsrc = B + (size_t)n0 * ldb + kt * 32;
#pragma unroll
        for (int p = 0; p < 2; p++) {
            int r = ldr + p * 64;
            cpasync16(stA + swz(r, ldc4), Asrc + (size_t)r * lda + ldc4 * 8);
        }
#pragma unroll
        for (int p = 0; p < 2; p++) {
            int r = ldr + p * 64;
            cpasync16(stB + swz(r, ldc4), Bsrc + (size_t)r * ldb + ldc4 * 8);
        }
    };

#pragma unroll
    for (int s = 0; s < 4; s++) { if (s < nk) load_stage(s); CP_COMMIT(); }

    float acc[4][4][4] = {};

    const int lrow = lane & 15;              // row within 16-row ldmatrix group
    const int chHalf = lane >> 4;            // 16B half within 32B k-slice

    for (int kt = 0; kt < nk; kt++) {
        CP_WAIT3();
        __syncthreads();
        if (kt + 4 < nk) load_stage(kt + 4);
        CP_COMMIT();

        uint32_t stA = sb + (kt % NSTG) * STG_B;
        uint32_t stB = stA + 8192;
#pragma unroll
        for (int kk = 0; kk < 2; kk++) {
            const int ch = kk * 2 + chHalf;
            uint32_t a[4][4], b[4][2];
#pragma unroll
            for (int i = 0; i < 4; i++) {
                int r = wm * 64 + i * 16 + lrow;
                ldsm4(a[i][0], a[i][1], a[i][2], a[i][3], stA + swz(r, ch));
            }
#pragma unroll
            for (int jp = 0; jp < 2; jp++) {
                int r = wn * 32 + jp * 16 + lrow;
                uint32_t t0, t1, t2, t3;
                ldsm4(t0, t1, t2, t3, stB + swz(r, ch));
                b[jp * 2][0] = t0; b[jp * 2 + 1][0] = t1;
                b[jp * 2][1] = t2; b[jp * 2 + 1][1] = t3;
            }
#pragma unroll
            for (int i = 0; i < 4; i++)
#pragma unroll
                for (int j = 0; j < 4; j++) mma168(acc[i][j], a[i], b[j]);
        }
    }

    // epilogue: direct global stores from accumulators
    const int er = lane >> 2, ec = (lane & 3) * 2;
    if (OUT16) {
        __half* C = (__half*)Cg + (long long)(z >> 3) * cO + (long long)(z & 7) * cI;
#pragma unroll
        for (int i = 0; i < 4; i++) {
            int r0 = m0 + wm * 64 + i * 16 + er;
#pragma unroll
            for (int j = 0; j < 4; j++) {
                int c0 = n0 + wn * 32 + j * 8 + ec;
                __half2 h01 = __floats2half2_rn(acc[i][j][0] * alpha, acc[i][j][1] * alpha);
                __half2 h23 = __floats2half2_rn(acc[i][j][2] * alpha, acc[i][j][3] * alpha);
                *(__half2*)(C + (size_t)r0 * ldc + c0) = h01;
                *(__half2*)(C + (size_t)(r0 + 8) * ldc + c0) = h23;
            }
        }
    } else {
        float* C = (float*)Cg + (long long)(z >> 3) * cO + (long long)(z & 7) * cI;
#pragma unroll
        for (int i = 0; i < 4; i++) {
            int r0 = m0 + wm * 64 + i * 16 + er;
#pragma unroll
            for (int j = 0; j < 4; j++) {
                int c0 = n0 + wn * 32 + j * 8 + ec;
                *(float2*)(C + (size_t)r0 * ldc + c0) =
                    make_float2(acc[i][j][0] * alpha, acc[i][j][1] * alpha);
                *(float2*)(C + (size_t)(r0 + 8) * ldc + c0) =
                    make_float2(acc[i][j][2] * alpha, acc[i][j][3] * alpha);
            }
        }
    }
}

// ---------------------------------------------------------------------------
// fp32 -> fp16 conversion
// ---------------------------------------------------------------------------
__global__ void f2h(const float4* __restrict__ in, uint2* __restrict__ outp, int n4) {
    int i = blockIdx.x * 256 + threadIdx.x;
    if (i < n4) {
        float4 v = in[i];
        __half2 a = __floats2half2_rn(v.x, v.y);
        __half2 b = __floats2half2_rn(v.z, v.w);
        outp[i] = make_uint2(*(uint32_t*)&a, *(uint32_t*)&b);
    }
}

// ---------------------------------------------------------------------------
// RoPE (fast-math-immune)
// ---------------------------------------------------------------------------
__device__ __forceinline__ void sincos_cw(float a, float* sp, float* cp) {
    float j = rintf(a * 0.63661977236758138f);
    int   q = (int)j;
    float r = fmaf(j, -1.5707962512969971e+00f, a);
    r = fmaf(j, -7.5497894158615964e-08f, r);
    r = fmaf(j, -5.3903029534742385e-15f, r);
    float x2 = r * r;
    float s = r * (1.f + x2 * (-1.6666667e-1f + x2 * (8.3333333e-3f +
                    x2 * (-1.9841270e-4f + x2 * 2.7557319e-6f))));
    float c = 1.f + x2 * (-0.5f + x2 * (4.1666667e-2f +
                    x2 * (-1.3888889e-3f + x2 * 2.4801587e-5f)));
    switch (q & 3) {
        case 0: *sp =  s; *cp =  c; break;
        case 1: *sp =  c; *cp = -s; break;
        case 2: *sp = -s; *cp = -c; break;
        default:*sp = -c; *cp =  s; break;
    }
}

__global__ void rope_table() {
    int idx = blockIdx.x * 256 + threadIdx.x;
    int d = idx & 255, t = idx >> 8;
    float e = (float)d * (1.0f / 256.0f);
    const float LH = 13.287712097167969f;
    const float LL = 2.8238148e-7f;
    float p = -fmaf(e, LH, e * LL);
    float nf = floorf(p);
    float f  = p - nf;
    float y  = f * 0.69314718055994531f;
    float er = 1.f + y * (1.f + y * (0.5f + y * (0.16666667f + y * (0.041666667f +
               y * (0.0083333333f + y * (0.0013888889f + y * (1.9841270e-4f +
               y * (2.4801587e-5f + y * 2.7557319e-6f))))))));
    float invf = er * __int_as_float(((int)nf + 127) << 23);
    float ang = (float)t * invf;
    float s, c;
    sincos_cw(ang, &s, &c);
    g_cos[idx] = c;
    g_sin[idx] = s;
}

// In-place RoPE on fp16 q and k (flat [b*T+t, h*D+d]), half-split pairs.
__global__ void rope_apply() {
    int idx = blockIdx.x * 256 + threadIdx.x;   // B*T*H*Dh
    int d = idx & 255;
    int h = (idx >> 8) & 7;
    int t = (idx >> 11) & 2047;
    int b = idx >> 22;
    float cc = g_cos[t * 256 + d], ss = g_sin[t * 256 + d];
    size_t base = ((size_t)(b * Tt + t)) * HDc + h * Dd + d;
    float x1 = __half2float(g_qh[base]), x2 = __half2float(g_qh[base + 256]);
    g_qh[base]       = __float2half_rn(x1 * cc - x2 * ss);
    g_qh[base + 256] = __float2half_rn(x1 * ss + x2 * cc);
    x1 = __half2float(g_kh[base]); x2 = __half2float(g_kh[base + 256]);
    g_kh[base]       = __float2half_rn(x1 * cc - x2 * ss);
    g_kh[base + 256] = __float2half_rn(x1 * ss + x2 * cc);
}

// ---------------------------------------------------------------------------
// Causal softmax on fp16 S; zero-pads probs to this row's 128 boundary.
// ---------------------------------------------------------------------------
__global__ void softmax_causal(__half2* __restrict__ S) {
    long long rr = blockIdx.x;
    long long zz = rr >> 11;
    int i = (int)(rr & 2047);
    __half2* row = S + zz * (Tt * Tt / 2) + (size_t)i * (Tt / 2);
    const int L = i + 1;
    const int tid = threadIdx.x;
    __shared__ float red[256];

    float v[8];
    float mx = -3.4e38f;
#pragma unroll
    for (int p = 0; p < 4; p++) {
        int j2 = tid + p * 256;
        float2 f = __half22float2(row[j2]);
        v[p * 2]     = (2 * j2     < L) ? f.x : -3.4e38f;
        v[p * 2 + 1] = (2 * j2 + 1 < L) ? f.y : -3.4e38f;
        mx = fmaxf(mx, fmaxf(v[p * 2], v[p * 2 + 1]));
    }
    red[tid] = mx; __syncthreads();
    for (int s = 128; s > 0; s >>= 1) {
        if (tid < s) red[tid] = fmaxf(red[tid], red[tid + s]);
        __syncthreads();
    }
    mx = red[0]; __syncthreads();

    float sum = 0.f;
#pragma unroll
    for (int p = 0; p < 8; p++) {
        float e = (v[p] > -1e38f) ? expf(v[p] - mx) : 0.f;
        v[p] = e;
        sum += e;
    }
    red[tid] = sum; __syncthreads();
    for (int s = 128; s > 0; s >>= 1) {
        if (tid < s) red[tid] += red[tid + s];
        __syncthreads();
    }
    float inv = 1.0f / red[0];

    const int Lpad = (L + 127) & ~127;
#pragma unroll
    for (int p = 0; p < 4; p++) {
        int j2 = tid + p * 256;
        if (2 * j2 < Lpad)
            row[j2] = __floats2half2_rn(v[p * 2] * inv, v[p * 2 + 1] * inv);
    }
}

// ---------------------------------------------------------------------------
extern "C" void kernel_launch(void* const* d_in, const int* in_sizes, int n_in,
                              void* d_out, int out_size) {
    const float* x  = (const float*)d_in[0];
    const float* Wq = (const float*)d_in[1];
    const float* Wk = (const float*)d_in[2];
    const float* Wv = (const float*)d_in[3];
    const float* Wo = (const float*)d_in[4];
    float* out = (float*)d_out;

    __half *xh, *wqh, *wkh, *wvh, *woh, *qh, *kh, *vTh, *attnh, *sh;
    cudaGetSymbolAddress((void**)&xh, g_xh);
    cudaGetSymbolAddress((void**)&wqh, g_wqh);
    cudaGetSymbolAddress((void**)&wkh, g_wkh);
    cudaGetSymbolAddress((void**)&wvh, g_wvh);
    cudaGetSymbolAddress((void**)&woh, g_woh);
    cudaGetSymbolAddress((void**)&qh, g_qh);
    cudaGetSymbolAddress((void**)&kh, g_kh);
    cudaGetSymbolAddress((void**)&vTh, g_vTh);
    cudaGetSymbolAddress((void**)&attnh, g_attnh);
    cudaGetSymbolAddress((void**)&sh, g_sh);

    cudaFuncSetAttribute(gemm_fp16<false, false, true>,
                         cudaFuncAttributeMaxDynamicSharedMemorySize, GEMM_SMEM);
    cudaFuncSetAttribute(gemm_fp16<true, false, true>,
                         cudaFuncAttributeMaxDynamicSharedMemorySize, GEMM_SMEM);
    cudaFuncSetAttribute(gemm_fp16<false, true, true>,
                         cudaFuncAttributeMaxDynamicSharedMemorySize, GEMM_SMEM);
    cudaFuncSetAttribute(gemm_fp16<false, false, false>,
                         cudaFuncAttributeMaxDynamicSharedMemorySize, GEMM_SMEM);

    dim3 blk(256);
    const long long TT  = (long long)Tt * Tt;
    const long long THD = (long long)Tt * HDc;

    // 0) convert raw fp32 inputs to fp16 scratch
    const int n4 = HDc * Ee / 4;
    f2h<<<n4 / 256, 256>>>((const float4*)x,  (uint2*)xh,  n4);
    f2h<<<n4 / 256, 256>>>((const float4*)Wq, (uint2*)wqh, n4);
    f2h<<<n4 / 256, 256>>>((const float4*)Wk, (uint2*)wkh, n4);
    f2h<<<n4 / 256, 256>>>((const float4*)Wv, (uint2*)wvh, n4);
    f2h<<<n4 / 256, 256>>>((const float4*)Wo, (uint2*)woh, n4);

    // 1) QKV projections (NT)
    gemm_fp16<false, false, true><<<dim3(32, 32, 1), blk, GEMM_SMEM>>>(
        xh, wqh, qh, Ee, Ee, Ee, HDc, 0, 0, 0, 0, 0, 0, 1.f);
    gemm_fp16<false, false, true><<<dim3(32, 32, 1), blk, GEMM_SMEM>>>(
        xh, wkh, kh, Ee, Ee, Ee, HDc, 0, 0, 0, 0, 0, 0, 1.f);
    // vT[hd, m] = Wv[hd,:] . x[m,:]
    gemm_fp16<false, false, true><<<dim3(32, 32, 1), blk, GEMM_SMEM>>>(
        wvh, xh, vTh, Ee, Ee, Ee, Mc, 0, 0, 0, 0, 0, 0, 1.f);

    // 2) RoPE on q, k
    rope_table<<<(Tt * Dh) / 256, 256>>>();
    rope_apply<<<(Bb * Tt * Hh * Dh) / 256, 256>>>();

    // 3) scores[b,h] = scale * q[b,h] @ k[b,h]^T   (causal tile skip)
    gemm_fp16<true, false, true><<<dim3(16, 16, Bb * Hh), blk, GEMM_SMEM>>>(
        qh, kh, sh, Dd, HDc, HDc, Tt,
        THD, (long long)Dd, THD, (long long)Dd,
        (long long)Hh * TT, TT, 0.044194173824159216f);

    // 4) causal softmax (fp16 in/out)
    softmax_causal<<<Bb * Hh * Tt, 256>>>((__half2*)sh);

    // 5) attn[b,h] = P[b,h] @ vT[b,h]^T   (NT, causal K limit)
    gemm_fp16<false, true, true><<<dim3(4, 16, Bb * Hh), blk, GEMM_SMEM>>>(
        sh, vTh, attnh, Tt, Tt, Mc, HDc,
        (long long)Hh * TT, TT,
        (long long)Tt, (long long)Dd * Mc,
        (long long)Tt * HDc, (long long)Dd, 1.f);

    // 6) out = attn_flat @ Wo^T  (fp32 output)
    gemm_fp16<false, false, false><<<dim3(8, 32, 1), blk, GEMM_SMEM>>>(
        attnh, woh, out, HDc, HDc, HDc, Ee, 0, 0, 0, 0, 0, 0, 1.f);
}